// round 5
// baseline (speedup 1.0000x reference)
#include <cuda_runtime.h>
#include <stdint.h>

#define N_NODES 50000
#define N_EDGES 400000
#define IN_FEAT 64
#define H_DIM 32

// ---- device scratch (no runtime allocation allowed) ----
__device__ float g_h[N_NODES * H_DIM];     // relu(x@lin0_w + lin0_b)
__device__ float g_S[N_NODES * H_DIM];     // scatter-sum of h[src] at dst
__device__ float g_out[N_NODES * H_DIM];   // node embeddings after NNConv
__device__ float g_We[H_DIM * H_DIM];      // shared per-edge weight matrix

__device__ __forceinline__ void red_add_v4(float* addr, float4 v) {
    asm volatile("red.global.v4.f32.add [%0], {%1, %2, %3, %4};"
                 :: "l"(addr), "f"(v.x), "f"(v.y), "f"(v.z), "f"(v.w)
                 : "memory");
}

__device__ __forceinline__ float relu(float v) { return v > 0.f ? v : 0.f; }

// ============================================================
// K0: W_edge = relu(nn_w1 + nn_b1) @ nn_w2 + nn_b2  (shared by all edges,
// since edge_attr == ones((E,1)))
// ============================================================
__global__ void k0_edge_weight(const float* __restrict__ nn_w1,
                               const float* __restrict__ nn_b1,
                               const float* __restrict__ nn_w2,
                               const float* __restrict__ nn_b2) {
    __shared__ float w1[H_DIM];
    int t = threadIdx.x;
    if (t < H_DIM) w1[t] = relu(nn_w1[t] + nn_b1[t]);
    __syncthreads();
    for (int i = t; i < H_DIM * H_DIM; i += blockDim.x) {
        float acc = nn_b2[i];
        #pragma unroll
        for (int k = 0; k < H_DIM; k++)
            acc += w1[k] * nn_w2[k * (H_DIM * H_DIM) + i];
        g_We[i] = acc;
    }
}

// ============================================================
// K1: h = relu(x @ lin0_w + lin0_b); S = 0.
// 4 threads per row; each computes 8 output cols (2 float4 accs).
// ============================================================
__global__ void __launch_bounds__(128) k1_lin0(
        const float* __restrict__ x,
        const float* __restrict__ lin0_w,
        const float* __restrict__ lin0_b,
        int n_nodes) {
    __shared__ float4 sw[IN_FEAT * 8];  // [k][j4], 8 KB
    __shared__ float4 sb[8];
    for (int i = threadIdx.x; i < IN_FEAT * 8; i += blockDim.x)
        sw[i] = ((const float4*)lin0_w)[i];
    if (threadIdx.x < 8) sb[threadIdx.x] = ((const float4*)lin0_b)[threadIdx.x];
    __syncthreads();

    int g = blockIdx.x * blockDim.x + threadIdx.x;
    int row = g >> 2;
    int jb  = (g & 3) * 2;          // float4 column base (2 float4 = 8 cols)
    if (row >= n_nodes) return;

    float4 a0 = sb[jb], a1 = sb[jb + 1];

    const float4* xr = (const float4*)(x + (size_t)row * IN_FEAT);
    #pragma unroll 4
    for (int q = 0; q < IN_FEAT / 4; q++) {
        float4 xc = __ldg(&xr[q]);
        #pragma unroll
        for (int i = 0; i < 4; i++) {
            float xk = (i == 0) ? xc.x : (i == 1) ? xc.y : (i == 2) ? xc.z : xc.w;
            const float4 w0 = sw[(q * 4 + i) * 8 + jb];
            const float4 w1 = sw[(q * 4 + i) * 8 + jb + 1];
            a0.x = fmaf(xk, w0.x, a0.x); a0.y = fmaf(xk, w0.y, a0.y);
            a0.z = fmaf(xk, w0.z, a0.z); a0.w = fmaf(xk, w0.w, a0.w);
            a1.x = fmaf(xk, w1.x, a1.x); a1.y = fmaf(xk, w1.y, a1.y);
            a1.z = fmaf(xk, w1.z, a1.z); a1.w = fmaf(xk, w1.w, a1.w);
        }
    }

    a0.x = relu(a0.x); a0.y = relu(a0.y); a0.z = relu(a0.z); a0.w = relu(a0.w);
    a1.x = relu(a1.x); a1.y = relu(a1.y); a1.z = relu(a1.z); a1.w = relu(a1.w);

    float4* hr = (float4*)(g_h + row * H_DIM);
    float4* Sr = (float4*)(g_S + row * H_DIM);
    const float4 z = make_float4(0.f, 0.f, 0.f, 0.f);
    hr[jb] = a0; hr[jb + 1] = a1;
    Sr[jb] = z;  Sr[jb + 1] = z;
}

// ============================================================
// K2: S[dst] += h[src]  — vector atomics. 8 threads per edge, each
// handles one float4 quarter via red.global.v4.f32.add.
// ============================================================
__global__ void k2_scatter(const int* __restrict__ edge_index,
                           int n_edges, int n_nodes) {
    long long tid = (long long)blockIdx.x * blockDim.x + threadIdx.x;
    int e = (int)(tid >> 3);
    if (e >= n_edges) return;
    int q = (int)(tid & 7);

    int src = __ldg(&edge_index[e]);            // edge_index[0][e]
    int dst = __ldg(&edge_index[n_edges + e]);  // edge_index[1][e]
    src = min(max(src, 0), n_nodes - 1);
    dst = min(max(dst, 0), n_nodes - 1);

    float4 v = __ldg((const float4*)(g_h + src * H_DIM) + q);
    red_add_v4(g_S + dst * H_DIM + q * 4, v);
}

// ============================================================
// K3: out = S @ W_edge + h @ conv_root + conv_bias
// 4 threads per row; each computes 8 output cols.
// ============================================================
__global__ void __launch_bounds__(128) k3_combine(
        const float* __restrict__ conv_root,
        const float* __restrict__ conv_bias,
        int n_nodes) {
    __shared__ float4 sWe[H_DIM * 8];  // 4 KB
    __shared__ float4 sWr[H_DIM * 8];  // 4 KB
    __shared__ float4 sb[8];
    for (int i = threadIdx.x; i < H_DIM * 8; i += blockDim.x) {
        sWe[i] = ((const float4*)g_We)[i];
        sWr[i] = ((const float4*)conv_root)[i];
    }
    if (threadIdx.x < 8) sb[threadIdx.x] = ((const float4*)conv_bias)[threadIdx.x];
    __syncthreads();

    int g = blockIdx.x * blockDim.x + threadIdx.x;
    int row = g >> 2;
    int jb  = (g & 3) * 2;
    if (row >= n_nodes) return;

    float4 a0 = sb[jb], a1 = sb[jb + 1];

    const float4* S4 = (const float4*)(g_S + row * H_DIM);
    const float4* h4 = (const float4*)(g_h + row * H_DIM);
    #pragma unroll 2
    for (int q = 0; q < H_DIM / 4; q++) {
        float4 sc = __ldg(&S4[q]);
        float4 hc = __ldg(&h4[q]);
        #pragma unroll
        for (int i = 0; i < 4; i++) {
            float sk = (i == 0) ? sc.x : (i == 1) ? sc.y : (i == 2) ? sc.z : sc.w;
            float hk = (i == 0) ? hc.x : (i == 1) ? hc.y : (i == 2) ? hc.z : hc.w;
            int k = q * 4 + i;
            const float4 we0 = sWe[k * 8 + jb];
            const float4 wr0 = sWr[k * 8 + jb];
            const float4 we1 = sWe[k * 8 + jb + 1];
            const float4 wr1 = sWr[k * 8 + jb + 1];
            a0.x = fmaf(sk, we0.x, fmaf(hk, wr0.x, a0.x));
            a0.y = fmaf(sk, we0.y, fmaf(hk, wr0.y, a0.y));
            a0.z = fmaf(sk, we0.z, fmaf(hk, wr0.z, a0.z));
            a0.w = fmaf(sk, we0.w, fmaf(hk, wr0.w, a0.w));
            a1.x = fmaf(sk, we1.x, fmaf(hk, wr1.x, a1.x));
            a1.y = fmaf(sk, we1.y, fmaf(hk, wr1.y, a1.y));
            a1.z = fmaf(sk, we1.z, fmaf(hk, wr1.z, a1.z));
            a1.w = fmaf(sk, we1.w, fmaf(hk, wr1.w, a1.w));
        }
    }

    float4* orow = (float4*)(g_out + row * H_DIM);
    orow[jb] = a0; orow[jb + 1] = a1;
}

// ============================================================
// K4: per-edge score.
// p = out[src]*out[dst]; t = relu(p @ lin1_w + lin1_b); score = t @ lin2_w + b2
// One thread per edge; weights read as LDS.128.
// ============================================================
__global__ void k4_score(const int* __restrict__ edge_index,
                         const float* __restrict__ lin1_w,
                         const float* __restrict__ lin1_b,
                         const float* __restrict__ lin2_w,
                         const float* __restrict__ lin2_b,
                         float* __restrict__ out_score,
                         int n_edges, int n_nodes) {
    __shared__ float4 sW1[H_DIM * 2];  // [j][2], row j of lin1_w as 2 float4
    __shared__ float4 sB1[2];
    __shared__ float4 sW2[2];
    __shared__ float  sB2;
    for (int i = threadIdx.x; i < H_DIM * 2; i += blockDim.x)
        sW1[i] = ((const float4*)lin1_w)[i];
    if (threadIdx.x < 2) {
        sB1[threadIdx.x] = ((const float4*)lin1_b)[threadIdx.x];
        sW2[threadIdx.x] = ((const float4*)lin2_w)[threadIdx.x];
        if (threadIdx.x == 0) sB2 = lin2_b[0];
    }
    __syncthreads();

    int e = blockIdx.x * blockDim.x + threadIdx.x;
    if (e >= n_edges) return;

    int src = __ldg(&edge_index[e]);
    int dst = __ldg(&edge_index[n_edges + e]);
    src = min(max(src, 0), n_nodes - 1);
    dst = min(max(dst, 0), n_nodes - 1);
    const float4* a4 = (const float4*)(g_out + src * H_DIM);
    const float4* b4 = (const float4*)(g_out + dst * H_DIM);

    float4 acc0 = sB1[0], acc1 = sB1[1];

    #pragma unroll
    for (int q = 0; q < H_DIM / 4; q++) {
        float4 a = __ldg(&a4[q]);
        float4 b = __ldg(&b4[q]);
        float p[4] = {a.x * b.x, a.y * b.y, a.z * b.z, a.w * b.w};
        #pragma unroll
        for (int i = 0; i < 4; i++) {
            int j = q * 4 + i;
            const float4 w0 = sW1[j * 2];
            const float4 w1 = sW1[j * 2 + 1];
            acc0.x = fmaf(p[i], w0.x, acc0.x); acc0.y = fmaf(p[i], w0.y, acc0.y);
            acc0.z = fmaf(p[i], w0.z, acc0.z); acc0.w = fmaf(p[i], w0.w, acc0.w);
            acc1.x = fmaf(p[i], w1.x, acc1.x); acc1.y = fmaf(p[i], w1.y, acc1.y);
            acc1.z = fmaf(p[i], w1.z, acc1.z); acc1.w = fmaf(p[i], w1.w, acc1.w);
        }
    }

    const float4 v0 = sW2[0], v1 = sW2[1];
    float score = sB2;
    score = fmaf(relu(acc0.x), v0.x, score);
    score = fmaf(relu(acc0.y), v0.y, score);
    score = fmaf(relu(acc0.z), v0.z, score);
    score = fmaf(relu(acc0.w), v0.w, score);
    score = fmaf(relu(acc1.x), v1.x, score);
    score = fmaf(relu(acc1.y), v1.y, score);
    score = fmaf(relu(acc1.z), v1.z, score);
    score = fmaf(relu(acc1.w), v1.w, score);
    out_score[e] = score;
}

// ============================================================
// launch
// ============================================================
extern "C" void kernel_launch(void* const* d_in, const int* in_sizes, int n_in,
                              void* d_out, int out_size) {
    const float* x          = (const float*)d_in[0];
    const int*   edge_index = (const int*)d_in[1];   // int64 in JAX -> int32 in harness
    const float* lin0_w     = (const float*)d_in[2];
    const float* lin0_b     = (const float*)d_in[3];
    const float* nn_w1      = (const float*)d_in[4];
    const float* nn_b1      = (const float*)d_in[5];
    const float* nn_w2      = (const float*)d_in[6];
    const float* nn_b2      = (const float*)d_in[7];
    const float* conv_root  = (const float*)d_in[8];
    const float* conv_bias  = (const float*)d_in[9];
    const float* lin1_w     = (const float*)d_in[10];
    const float* lin1_b     = (const float*)d_in[11];
    const float* lin2_w     = (const float*)d_in[12];
    const float* lin2_b     = (const float*)d_in[13];
    float* out_score = (float*)d_out;

    int n_nodes = in_sizes[0] / IN_FEAT;
    int n_edges = in_sizes[1] / 2;

    // K0: shared edge weight matrix (tiny)
    k0_edge_weight<<<1, 256>>>(nn_w1, nn_b1, nn_w2, nn_b2);

    // K1: 4 threads per row
    {
        long long total = (long long)n_nodes * 4;
        int blocks = (int)((total + 127) / 128);
        k1_lin0<<<blocks, 128>>>(x, lin0_w, lin0_b, n_nodes);
    }

    // K2: 8 threads per edge, float4 reductions
    {
        long long total = (long long)n_edges * 8;
        int blocks = (int)((total + 255) / 256);
        k2_scatter<<<blocks, 256>>>(edge_index, n_edges, n_nodes);
    }

    // K3: 4 threads per row
    {
        long long total = (long long)n_nodes * 4;
        int blocks = (int)((total + 127) / 128);
        k3_combine<<<blocks, 128>>>(conv_root, conv_bias, n_nodes);
    }

    // K4: thread per edge
    {
        int blocks = (n_edges + 255) / 256;
        k4_score<<<blocks, 256>>>(edge_index, lin1_w, lin1_b, lin2_w, lin2_b,
                                  out_score, n_edges, n_nodes);
    }
}

// round 7
// speedup vs baseline: 1.4836x; 1.4836x over previous
#include <cuda_runtime.h>
#include <stdint.h>

#define N_NODES 50000
#define N_EDGES 400000
#define IN_FEAT 64
#define H_DIM 32
#define TILE_R 128
#define TILE_E 256

// ---- device scratch (no runtime allocation allowed) ----
__device__ float g_h[N_NODES * H_DIM];     // relu(x@lin0_w + lin0_b)
__device__ float g_S[N_NODES * H_DIM];     // scatter-sum of h[src] at dst
__device__ float g_out[N_NODES * H_DIM];   // node embeddings after NNConv
__device__ float g_We[H_DIM * H_DIM];      // shared per-edge weight matrix

__device__ __forceinline__ void red_add_v4(float* addr, float4 v) {
    asm volatile("red.global.v4.f32.add [%0], {%1, %2, %3, %4};"
                 :: "l"(addr), "f"(v.x), "f"(v.y), "f"(v.z), "f"(v.w)
                 : "memory");
}
__device__ __forceinline__ float relu(float v) { return v > 0.f ? v : 0.f; }

// XOR swizzle for transposed smem tiles: keeps float4 alignment (low 2 bits
// of row index untouched) while spreading banks across k.
__device__ __forceinline__ int swz(int k, int r) {
    return k * TILE_R + (r ^ (k & 28));
}

// ============================================================
// K0: W_edge = relu(nn_w1 + nn_b1) @ nn_w2 + nn_b2  (shared by all edges,
// since edge_attr == ones((E,1)))
// ============================================================
__global__ void k0_edge_weight(const float* __restrict__ nn_w1,
                               const float* __restrict__ nn_b1,
                               const float* __restrict__ nn_w2,
                               const float* __restrict__ nn_b2) {
    __shared__ float w1[H_DIM];
    int t = threadIdx.x;
    if (t < H_DIM) w1[t] = relu(nn_w1[t] + nn_b1[t]);
    __syncthreads();
    for (int i = t; i < H_DIM * H_DIM; i += blockDim.x) {
        float acc = nn_b2[i];
        #pragma unroll
        for (int k = 0; k < H_DIM; k++)
            acc += w1[k] * nn_w2[k * (H_DIM * H_DIM) + i];
        g_We[i] = acc;
    }
}

// ============================================================
// K1: h = relu(x @ lin0_w + lin0_b); S = 0.
// Lane j holds lin0_w[:,j] in 64 regs. x tile staged transposed in smem
// (coalesced LDG.128 in, broadcast LDS.128 out). Warp computes 4 rows at a
// time; stores coalesced STG.32.
// ============================================================
__global__ void __launch_bounds__(256) k1_lin0(
        const float* __restrict__ x,
        const float* __restrict__ lin0_w,
        const float* __restrict__ lin0_b,
        int n_nodes) {
    __shared__ float xT[IN_FEAT * TILE_R];  // 32 KB, transposed + swizzled

    int tid  = threadIdx.x;
    int lane = tid & 31;
    int wid  = tid >> 5;
    int row0 = blockIdx.x * TILE_R;

    // weight column j = lane, in registers (coalesced loads: one 128B line per k)
    float rW[IN_FEAT];
    #pragma unroll
    for (int k = 0; k < IN_FEAT; k++) rW[k] = __ldg(&lin0_w[k * H_DIM + lane]);
    float bj = __ldg(&lin0_b[lane]);

    // stage x tile transposed: 128 rows x 16 float4 = 2048 f4, 8 per thread
    #pragma unroll
    for (int it = 0; it < 8; it++) {
        int m = tid + 256 * it;
        int r = m >> 4, q = m & 15;
        float4 v = make_float4(0.f, 0.f, 0.f, 0.f);
        if (row0 + r < n_nodes)
            v = __ldg((const float4*)(x + (size_t)(row0 + r) * IN_FEAT) + q);
        xT[swz(4 * q + 0, r)] = v.x;
        xT[swz(4 * q + 1, r)] = v.y;
        xT[swz(4 * q + 2, r)] = v.z;
        xT[swz(4 * q + 3, r)] = v.w;
    }
    __syncthreads();

    // each warp computes 16 rows as 4 blocks of 4
    int wbase = wid * 16;
    #pragma unroll
    for (int sb = 0; sb < 4; sb++) {
        int rb = wbase + sb * 4;
        float a0 = bj, a1 = bj, a2 = bj, a3 = bj;
        #pragma unroll
        for (int k = 0; k < IN_FEAT; k++) {
            float4 xv = *(const float4*)&xT[swz(k, rb)];  // broadcast LDS.128
            a0 = fmaf(xv.x, rW[k], a0);
            a1 = fmaf(xv.y, rW[k], a1);
            a2 = fmaf(xv.z, rW[k], a2);
            a3 = fmaf(xv.w, rW[k], a3);
        }
        int gr = row0 + rb;
        float res[4] = {relu(a0), relu(a1), relu(a2), relu(a3)};
        #pragma unroll
        for (int i = 0; i < 4; i++) {
            if (gr + i < n_nodes) {
                g_h[(gr + i) * H_DIM + lane] = res[i];  // coalesced STG.32
                g_S[(gr + i) * H_DIM + lane] = 0.f;
            }
        }
    }
}

// ============================================================
// K2: S[dst] += h[src]  — vector atomics. 8 threads per edge, each
// handles one float4 quarter via red.global.v4.f32.add.
// ============================================================
__global__ void k2_scatter(const int* __restrict__ edge_index,
                           int n_edges, int n_nodes) {
    long long tid = (long long)blockIdx.x * blockDim.x + threadIdx.x;
    int e = (int)(tid >> 3);
    if (e >= n_edges) return;
    int q = (int)(tid & 7);

    int src = __ldg(&edge_index[e]);            // edge_index[0][e]
    int dst = __ldg(&edge_index[n_edges + e]);  // edge_index[1][e]
    src = min(max(src, 0), n_nodes - 1);
    dst = min(max(dst, 0), n_nodes - 1);

    float4 v = __ldg((const float4*)(g_h + src * H_DIM) + q);
    red_add_v4(g_S + dst * H_DIM + q * 4, v);
}

// ============================================================
// K3: out = S @ W_edge + h @ conv_root + conv_bias
// Lane j holds We[:,j] and Wr[:,j] in 64 regs. S/h tiles staged transposed.
// ============================================================
__global__ void __launch_bounds__(256) k3_combine(
        const float* __restrict__ conv_root,
        const float* __restrict__ conv_bias,
        int n_nodes) {
    __shared__ float sT[H_DIM * TILE_R];  // 16 KB
    __shared__ float hT[H_DIM * TILE_R];  // 16 KB

    int tid  = threadIdx.x;
    int lane = tid & 31;
    int wid  = tid >> 5;
    int row0 = blockIdx.x * TILE_R;

    float rWe[H_DIM], rWr[H_DIM];
    #pragma unroll
    for (int k = 0; k < H_DIM; k++) {
        rWe[k] = g_We[k * H_DIM + lane];
        rWr[k] = __ldg(&conv_root[k * H_DIM + lane]);
    }
    float bj = __ldg(&conv_bias[lane]);

    // stage S and h tiles transposed: 128 rows x 8 f4 = 1024 f4 each, 4/thread
    #pragma unroll
    for (int it = 0; it < 4; it++) {
        int m = tid + 256 * it;
        int r = m >> 3, q = m & 7;
        float4 sv = make_float4(0.f, 0.f, 0.f, 0.f);
        float4 hv = make_float4(0.f, 0.f, 0.f, 0.f);
        if (row0 + r < n_nodes) {
            sv = __ldg((const float4*)(g_S + (size_t)(row0 + r) * H_DIM) + q);
            hv = __ldg((const float4*)(g_h + (size_t)(row0 + r) * H_DIM) + q);
        }
        sT[swz(4 * q + 0, r)] = sv.x;  hT[swz(4 * q + 0, r)] = hv.x;
        sT[swz(4 * q + 1, r)] = sv.y;  hT[swz(4 * q + 1, r)] = hv.y;
        sT[swz(4 * q + 2, r)] = sv.z;  hT[swz(4 * q + 2, r)] = hv.z;
        sT[swz(4 * q + 3, r)] = sv.w;  hT[swz(4 * q + 3, r)] = hv.w;
    }
    __syncthreads();

    int wbase = wid * 16;
    #pragma unroll
    for (int sb = 0; sb < 4; sb++) {
        int rb = wbase + sb * 4;
        float a0 = bj, a1 = bj, a2 = bj, a3 = bj;
        #pragma unroll
        for (int k = 0; k < H_DIM; k++) {
            float4 sv = *(const float4*)&sT[swz(k, rb)];  // broadcast
            float4 hv = *(const float4*)&hT[swz(k, rb)];  // broadcast
            a0 = fmaf(sv.x, rWe[k], fmaf(hv.x, rWr[k], a0));
            a1 = fmaf(sv.y, rWe[k], fmaf(hv.y, rWr[k], a1));
            a2 = fmaf(sv.z, rWe[k], fmaf(hv.z, rWr[k], a2));
            a3 = fmaf(sv.w, rWe[k], fmaf(hv.w, rWr[k], a3));
        }
        int gr = row0 + rb;
        float res[4] = {a0, a1, a2, a3};
        #pragma unroll
        for (int i = 0; i < 4; i++)
            if (gr + i < n_nodes)
                g_out[(gr + i) * H_DIM + lane] = res[i];  // coalesced STG.32
    }
}

// ============================================================
// K4: per-edge score, two-phase.
// Phase A: 8 lanes per edge gather out[src],out[dst] as whole coalesced
//          128B lines, form p = a*b, store to swizzled smem.
// Phase B: thread per edge: p@W1 (+bias, relu) then dot with W2.
// ============================================================
__global__ void __launch_bounds__(256) k4_score(
        const int* __restrict__ edge_index,
        const float* __restrict__ lin1_w,
        const float* __restrict__ lin1_b,
        const float* __restrict__ lin2_w,
        const float* __restrict__ lin2_b,
        float* __restrict__ out_score,
        int n_edges, int n_nodes) {
    __shared__ int   s_src[TILE_E];
    __shared__ int   s_dst[TILE_E];
    __shared__ float pT[TILE_E * H_DIM];      // 32 KB, swizzled
    __shared__ float sW1[H_DIM * 8];          // row-major [k][j]
    __shared__ float sB1[8], sW2[8];
    __shared__ float sB2;

    int tid = threadIdx.x;
    if (tid < H_DIM * 8) sW1[tid] = lin1_w[tid];
    if (tid < 8) { sB1[tid] = lin1_b[tid]; sW2[tid] = lin2_w[tid]; }
    if (tid == 0) sB2 = lin2_b[0];

    int e0 = blockIdx.x * TILE_E;
    {
        int e = e0 + tid;
        int s = 0, d = 0;
        if (e < n_edges) {
            s = min(max(__ldg(&edge_index[e]), 0), n_nodes - 1);
            d = min(max(__ldg(&edge_index[n_edges + e]), 0), n_nodes - 1);
        }
        s_src[tid] = s;
        s_dst[tid] = d;
    }
    __syncthreads();

    // Phase A: 2048 f4 (256 edges x 8 quarters), 8 per thread.
    // Lanes 0-7 cover one edge's full row -> 1 line per row per LDG instr.
    #pragma unroll
    for (int it = 0; it < 8; it++) {
        int m = tid + 256 * it;
        int el = m >> 3, q = m & 7;
        int s = s_src[el], d = s_dst[el];
        float4 a = __ldg((const float4*)(g_out + (size_t)s * H_DIM) + q);
        float4 b = __ldg((const float4*)(g_out + (size_t)d * H_DIM) + q);
        float4 p = make_float4(a.x * b.x, a.y * b.y, a.z * b.z, a.w * b.w);
        *(float4*)&pT[el * H_DIM + 4 * (q ^ (el & 7))] = p;
    }
    __syncthreads();

    // Phase B: thread per edge
    float p[H_DIM];
    #pragma unroll
    for (int q = 0; q < 8; q++) {
        float4 v = *(const float4*)&pT[tid * H_DIM + 4 * (q ^ (tid & 7))];
        p[4 * q + 0] = v.x; p[4 * q + 1] = v.y;
        p[4 * q + 2] = v.z; p[4 * q + 3] = v.w;
    }

    float acc[8];
    #pragma unroll
    for (int j = 0; j < 8; j++) acc[j] = sB1[j];
    #pragma unroll
    for (int k = 0; k < H_DIM; k++) {
        float4 w0 = *(const float4*)&sW1[k * 8];      // broadcast LDS.128
        float4 w1 = *(const float4*)&sW1[k * 8 + 4];  // broadcast LDS.128
        float pk = p[k];
        acc[0] = fmaf(pk, w0.x, acc[0]); acc[1] = fmaf(pk, w0.y, acc[1]);
        acc[2] = fmaf(pk, w0.z, acc[2]); acc[3] = fmaf(pk, w0.w, acc[3]);
        acc[4] = fmaf(pk, w1.x, acc[4]); acc[5] = fmaf(pk, w1.y, acc[5]);
        acc[6] = fmaf(pk, w1.z, acc[6]); acc[7] = fmaf(pk, w1.w, acc[7]);
    }

    float score = sB2;
    #pragma unroll
    for (int j = 0; j < 8; j++) score = fmaf(relu(acc[j]), sW2[j], score);

    int e = e0 + tid;
    if (e < n_edges) out_score[e] = score;  // coalesced STG.32
}

// ============================================================
// launch
// ============================================================
extern "C" void kernel_launch(void* const* d_in, const int* in_sizes, int n_in,
                              void* d_out, int out_size) {
    const float* x          = (const float*)d_in[0];
    const int*   edge_index = (const int*)d_in[1];   // int64 in JAX -> int32 in harness
    const float* lin0_w     = (const float*)d_in[2];
    const float* lin0_b     = (const float*)d_in[3];
    const float* nn_w1      = (const float*)d_in[4];
    const float* nn_b1      = (const float*)d_in[5];
    const float* nn_w2      = (const float*)d_in[6];
    const float* nn_b2      = (const float*)d_in[7];
    const float* conv_root  = (const float*)d_in[8];
    const float* conv_bias  = (const float*)d_in[9];
    const float* lin1_w     = (const float*)d_in[10];
    const float* lin1_b     = (const float*)d_in[11];
    const float* lin2_w     = (const float*)d_in[12];
    const float* lin2_b     = (const float*)d_in[13];
    float* out_score = (float*)d_out;

    int n_nodes = in_sizes[0] / IN_FEAT;
    int n_edges = in_sizes[1] / 2;

    // K0: shared edge weight matrix (tiny)
    k0_edge_weight<<<1, 256>>>(nn_w1, nn_b1, nn_w2, nn_b2);

    // K1: 128-row tiles, 256 threads
    {
        int blocks = (n_nodes + TILE_R - 1) / TILE_R;
        k1_lin0<<<blocks, 256>>>(x, lin0_w, lin0_b, n_nodes);
    }

    // K2: 8 threads per edge, float4 reductions
    {
        long long total = (long long)n_edges * 8;
        int blocks = (int)((total + 255) / 256);
        k2_scatter<<<blocks, 256>>>(edge_index, n_edges, n_nodes);
    }

    // K3: 128-row tiles, 256 threads
    {
        int blocks = (n_nodes + TILE_R - 1) / TILE_R;
        k3_combine<<<blocks, 256>>>(conv_root, conv_bias, n_nodes);
    }

    // K4: 256-edge tiles, 256 threads
    {
        int blocks = (n_edges + TILE_E - 1) / TILE_E;
        k4_score<<<blocks, 256>>>(edge_index, lin1_w, lin1_b, lin2_w, lin2_b,
                                  out_score, n_edges, n_nodes);
    }
}

// round 8
// speedup vs baseline: 1.6425x; 1.1071x over previous
#include <cuda_runtime.h>
#include <stdint.h>

#define N_NODES 50000
#define N_EDGES 400000
#define IN_FEAT 64
#define H_DIM 32
#define TILE_R 128
#define TILE_E 256

// ---- device scratch (no runtime allocation allowed) ----
__device__ float g_h[N_NODES * H_DIM];     // relu(x@lin0_w + lin0_b)
__device__ float g_S[N_NODES * H_DIM];     // scatter-sum of h[src] at dst
__device__ float g_out[N_NODES * H_DIM];   // node embeddings after NNConv
__device__ float g_We[H_DIM * H_DIM];      // shared per-edge weight matrix

__device__ __forceinline__ void red_add_v4(float* addr, float4 v) {
    asm volatile("red.global.v4.f32.add [%0], {%1, %2, %3, %4};"
                 :: "l"(addr), "f"(v.x), "f"(v.y), "f"(v.z), "f"(v.w)
                 : "memory");
}
__device__ __forceinline__ float relu(float v) { return v > 0.f ? v : 0.f; }

// XOR swizzle for transposed smem tiles: keeps float4 alignment (low 2 bits
// of row index untouched) while spreading banks across k.
__device__ __forceinline__ int swz(int k, int r) {
    return k * TILE_R + (r ^ (k & 28));
}

// ============================================================
// K0: W_edge = relu(nn_w1 + nn_b1) @ nn_w2 + nn_b2  (shared by all edges,
// since edge_attr == ones((E,1)))
// ============================================================
__global__ void k0_edge_weight(const float* __restrict__ nn_w1,
                               const float* __restrict__ nn_b1,
                               const float* __restrict__ nn_w2,
                               const float* __restrict__ nn_b2) {
    __shared__ float w1[H_DIM];
    int t = threadIdx.x;
    if (t < H_DIM) w1[t] = relu(nn_w1[t] + nn_b1[t]);
    __syncthreads();
    for (int i = t; i < H_DIM * H_DIM; i += blockDim.x) {
        float acc = nn_b2[i];
        #pragma unroll
        for (int k = 0; k < H_DIM; k++)
            acc += w1[k] * nn_w2[k * (H_DIM * H_DIM) + i];
        g_We[i] = acc;
    }
}

// ============================================================
// K1: h = relu(x @ lin0_w + lin0_b); S = 0.
// Register-tiled GEMM: thread = 4 rows x 4 cols micro-tile.
// tx = tid&7 -> col group, ty = tid>>3 -> row group.
// Per k: 1 broadcast LDS.128 (rows) + 1 conflict-free LDS.128 (weights),
// 16 FFMA. ~40 regs -> high occupancy.
// ============================================================
__global__ void __launch_bounds__(256) k1_lin0(
        const float* __restrict__ x,
        const float* __restrict__ lin0_w,
        const float* __restrict__ lin0_b,
        int n_nodes) {
    __shared__ float xT[IN_FEAT * TILE_R];   // 32 KB, transposed + swizzled
    __shared__ float4 sw[IN_FEAT * 8];       // 8 KB, [k][j4]
    __shared__ float4 sb[8];

    int tid  = threadIdx.x;
    int tx   = tid & 7;
    int ty   = tid >> 3;
    int row0 = blockIdx.x * TILE_R;

    // weights + bias to smem
    #pragma unroll
    for (int it = 0; it < 2; it++)
        sw[tid + 256 * it] = ((const float4*)lin0_w)[tid + 256 * it];
    if (tid < 8) sb[tid] = ((const float4*)lin0_b)[tid];

    // stage x tile transposed: 128 rows x 16 float4 = 2048 f4, 8 per thread
    #pragma unroll
    for (int it = 0; it < 8; it++) {
        int m = tid + 256 * it;
        int r = m >> 4, q = m & 15;
        float4 v = make_float4(0.f, 0.f, 0.f, 0.f);
        if (row0 + r < n_nodes)
            v = __ldg((const float4*)(x + (size_t)(row0 + r) * IN_FEAT) + q);
        xT[swz(4 * q + 0, r)] = v.x;
        xT[swz(4 * q + 1, r)] = v.y;
        xT[swz(4 * q + 2, r)] = v.z;
        xT[swz(4 * q + 3, r)] = v.w;
    }
    __syncthreads();

    float4 bv = sb[tx];
    float4 acc0 = bv, acc1 = bv, acc2 = bv, acc3 = bv;
    int rb = ty * 4;

    #pragma unroll 8
    for (int k = 0; k < IN_FEAT; k++) {
        float4 xv = *(const float4*)&xT[swz(k, rb)];  // 4 rows' k-values
        float4 wv = sw[k * 8 + tx];                   // 4 cols' weights
        acc0.x = fmaf(xv.x, wv.x, acc0.x); acc0.y = fmaf(xv.x, wv.y, acc0.y);
        acc0.z = fmaf(xv.x, wv.z, acc0.z); acc0.w = fmaf(xv.x, wv.w, acc0.w);
        acc1.x = fmaf(xv.y, wv.x, acc1.x); acc1.y = fmaf(xv.y, wv.y, acc1.y);
        acc1.z = fmaf(xv.y, wv.z, acc1.z); acc1.w = fmaf(xv.y, wv.w, acc1.w);
        acc2.x = fmaf(xv.z, wv.x, acc2.x); acc2.y = fmaf(xv.z, wv.y, acc2.y);
        acc2.z = fmaf(xv.z, wv.z, acc2.z); acc2.w = fmaf(xv.z, wv.w, acc2.w);
        acc3.x = fmaf(xv.w, wv.x, acc3.x); acc3.y = fmaf(xv.w, wv.y, acc3.y);
        acc3.z = fmaf(xv.w, wv.z, acc3.z); acc3.w = fmaf(xv.w, wv.w, acc3.w);
    }

    const float4 z = make_float4(0.f, 0.f, 0.f, 0.f);
    float4 res[4] = {acc0, acc1, acc2, acc3};
    #pragma unroll
    for (int i = 0; i < 4; i++) {
        int gr = row0 + rb + i;
        if (gr < n_nodes) {
            float4 a = res[i];
            a.x = relu(a.x); a.y = relu(a.y); a.z = relu(a.z); a.w = relu(a.w);
            *(float4*)(g_h + (size_t)gr * H_DIM + tx * 4) = a;
            *(float4*)(g_S + (size_t)gr * H_DIM + tx * 4) = z;
        }
    }
}

// ============================================================
// K2: S[dst] += h[src]  — vector atomics. 8 threads per edge, each
// handles one float4 quarter via red.global.v4.f32.add.
// ============================================================
__global__ void k2_scatter(const int* __restrict__ edge_index,
                           int n_edges, int n_nodes) {
    long long tid = (long long)blockIdx.x * blockDim.x + threadIdx.x;
    int e = (int)(tid >> 3);
    if (e >= n_edges) return;
    int q = (int)(tid & 7);

    int src = __ldg(&edge_index[e]);            // edge_index[0][e]
    int dst = __ldg(&edge_index[n_edges + e]);  // edge_index[1][e]
    src = min(max(src, 0), n_nodes - 1);
    dst = min(max(dst, 0), n_nodes - 1);

    float4 v = __ldg((const float4*)(g_h + src * H_DIM) + q);
    red_add_v4(g_S + dst * H_DIM + q * 4, v);
}

// ============================================================
// K3: out = S @ W_edge + h @ conv_root + conv_bias
// Register-tiled: thread = 4 rows x 4 cols, two input matrices.
// Per k: 2 broadcast LDS.128 (S,h rows) + 2 LDS.128 (weights), 32 FFMA.
// ============================================================
__global__ void __launch_bounds__(256) k3_combine(
        const float* __restrict__ conv_root,
        const float* __restrict__ conv_bias,
        int n_nodes) {
    __shared__ float sT[H_DIM * TILE_R];   // 16 KB
    __shared__ float hT[H_DIM * TILE_R];   // 16 KB
    __shared__ float4 sWe[H_DIM * 8];      // 4 KB
    __shared__ float4 sWr[H_DIM * 8];      // 4 KB
    __shared__ float4 sb[8];

    int tid  = threadIdx.x;
    int tx   = tid & 7;
    int ty   = tid >> 3;
    int row0 = blockIdx.x * TILE_R;

    sWe[tid] = ((const float4*)g_We)[tid];
    sWr[tid] = ((const float4*)conv_root)[tid];
    if (tid < 8) sb[tid] = ((const float4*)conv_bias)[tid];

    // stage S and h tiles transposed: 128 rows x 8 f4 = 1024 f4 each, 4/thread
    #pragma unroll
    for (int it = 0; it < 4; it++) {
        int m = tid + 256 * it;
        int r = m >> 3, q = m & 7;
        float4 sv = make_float4(0.f, 0.f, 0.f, 0.f);
        float4 hv = make_float4(0.f, 0.f, 0.f, 0.f);
        if (row0 + r < n_nodes) {
            sv = __ldg((const float4*)(g_S + (size_t)(row0 + r) * H_DIM) + q);
            hv = __ldg((const float4*)(g_h + (size_t)(row0 + r) * H_DIM) + q);
        }
        sT[swz(4 * q + 0, r)] = sv.x;  hT[swz(4 * q + 0, r)] = hv.x;
        sT[swz(4 * q + 1, r)] = sv.y;  hT[swz(4 * q + 1, r)] = hv.y;
        sT[swz(4 * q + 2, r)] = sv.z;  hT[swz(4 * q + 2, r)] = hv.z;
        sT[swz(4 * q + 3, r)] = sv.w;  hT[swz(4 * q + 3, r)] = hv.w;
    }
    __syncthreads();

    float4 bv = sb[tx];
    float4 acc0 = bv, acc1 = bv, acc2 = bv, acc3 = bv;
    int rb = ty * 4;

    #pragma unroll 8
    for (int k = 0; k < H_DIM; k++) {
        float4 sv = *(const float4*)&sT[swz(k, rb)];
        float4 hv = *(const float4*)&hT[swz(k, rb)];
        float4 we = sWe[k * 8 + tx];
        float4 wr = sWr[k * 8 + tx];
        acc0.x = fmaf(sv.x, we.x, fmaf(hv.x, wr.x, acc0.x));
        acc0.y = fmaf(sv.x, we.y, fmaf(hv.x, wr.y, acc0.y));
        acc0.z = fmaf(sv.x, we.z, fmaf(hv.x, wr.z, acc0.z));
        acc0.w = fmaf(sv.x, we.w, fmaf(hv.x, wr.w, acc0.w));
        acc1.x = fmaf(sv.y, we.x, fmaf(hv.y, wr.x, acc1.x));
        acc1.y = fmaf(sv.y, we.y, fmaf(hv.y, wr.y, acc1.y));
        acc1.z = fmaf(sv.y, we.z, fmaf(hv.y, wr.z, acc1.z));
        acc1.w = fmaf(sv.y, we.w, fmaf(hv.y, wr.w, acc1.w));
        acc2.x = fmaf(sv.z, we.x, fmaf(hv.z, wr.x, acc2.x));
        acc2.y = fmaf(sv.z, we.y, fmaf(hv.z, wr.y, acc2.y));
        acc2.z = fmaf(sv.z, we.z, fmaf(hv.z, wr.z, acc2.z));
        acc2.w = fmaf(sv.z, we.w, fmaf(hv.z, wr.w, acc2.w));
        acc3.x = fmaf(sv.w, we.x, fmaf(hv.w, wr.x, acc3.x));
        acc3.y = fmaf(sv.w, we.y, fmaf(hv.w, wr.y, acc3.y));
        acc3.z = fmaf(sv.w, we.z, fmaf(hv.w, wr.z, acc3.z));
        acc3.w = fmaf(sv.w, we.w, fmaf(hv.w, wr.w, acc3.w));
    }

    float4 res[4] = {acc0, acc1, acc2, acc3};
    #pragma unroll
    for (int i = 0; i < 4; i++) {
        int gr = row0 + rb + i;
        if (gr < n_nodes)
            *(float4*)(g_out + (size_t)gr * H_DIM + tx * 4) = res[i];
    }
}

// ============================================================
// K4: per-edge score, two-phase.
// Phase A: 8 lanes per edge gather out[src],out[dst] as whole coalesced
//          128B lines, form p = a*b, store to swizzled smem.
// Phase B: thread per edge: p@W1 (+bias, relu) then dot with W2.
// ============================================================
__global__ void __launch_bounds__(256) k4_score(
        const int* __restrict__ edge_index,
        const float* __restrict__ lin1_w,
        const float* __restrict__ lin1_b,
        const float* __restrict__ lin2_w,
        const float* __restrict__ lin2_b,
        float* __restrict__ out_score,
        int n_edges, int n_nodes) {
    __shared__ int   s_src[TILE_E];
    __shared__ int   s_dst[TILE_E];
    __shared__ float pT[TILE_E * H_DIM];      // 32 KB, swizzled
    __shared__ float sW1[H_DIM * 8];          // row-major [k][j]
    __shared__ float sB1[8], sW2[8];
    __shared__ float sB2;

    int tid = threadIdx.x;
    if (tid < H_DIM * 8) sW1[tid] = lin1_w[tid];
    if (tid < 8) { sB1[tid] = lin1_b[tid]; sW2[tid] = lin2_w[tid]; }
    if (tid == 0) sB2 = lin2_b[0];

    int e0 = blockIdx.x * TILE_E;
    {
        int e = e0 + tid;
        int s = 0, d = 0;
        if (e < n_edges) {
            s = min(max(__ldg(&edge_index[e]), 0), n_nodes - 1);
            d = min(max(__ldg(&edge_index[n_edges + e]), 0), n_nodes - 1);
        }
        s_src[tid] = s;
        s_dst[tid] = d;
    }
    __syncthreads();

    // Phase A: 2048 f4 (256 edges x 8 quarters), 8 per thread.
    #pragma unroll
    for (int it = 0; it < 8; it++) {
        int m = tid + 256 * it;
        int el = m >> 3, q = m & 7;
        int s = s_src[el], d = s_dst[el];
        float4 a = __ldg((const float4*)(g_out + (size_t)s * H_DIM) + q);
        float4 b = __ldg((const float4*)(g_out + (size_t)d * H_DIM) + q);
        float4 p = make_float4(a.x * b.x, a.y * b.y, a.z * b.z, a.w * b.w);
        *(float4*)&pT[el * H_DIM + 4 * (q ^ (el & 7))] = p;
    }
    __syncthreads();

    // Phase B: thread per edge
    float p[H_DIM];
    #pragma unroll
    for (int q = 0; q < 8; q++) {
        float4 v = *(const float4*)&pT[tid * H_DIM + 4 * (q ^ (tid & 7))];
        p[4 * q + 0] = v.x; p[4 * q + 1] = v.y;
        p[4 * q + 2] = v.z; p[4 * q + 3] = v.w;
    }

    float acc[8];
    #pragma unroll
    for (int j = 0; j < 8; j++) acc[j] = sB1[j];
    #pragma unroll
    for (int k = 0; k < H_DIM; k++) {
        float4 w0 = *(const float4*)&sW1[k * 8];      // broadcast LDS.128
        float4 w1 = *(const float4*)&sW1[k * 8 + 4];  // broadcast LDS.128
        float pk = p[k];
        acc[0] = fmaf(pk, w0.x, acc[0]); acc[1] = fmaf(pk, w0.y, acc[1]);
        acc[2] = fmaf(pk, w0.z, acc[2]); acc[3] = fmaf(pk, w0.w, acc[3]);
        acc[4] = fmaf(pk, w1.x, acc[4]); acc[5] = fmaf(pk, w1.y, acc[5]);
        acc[6] = fmaf(pk, w1.z, acc[6]); acc[7] = fmaf(pk, w1.w, acc[7]);
    }

    float score = sB2;
    #pragma unroll
    for (int j = 0; j < 8; j++) score = fmaf(relu(acc[j]), sW2[j], score);

    int e = e0 + tid;
    if (e < n_edges) out_score[e] = score;  // coalesced STG.32
}

// ============================================================
// launch
// ============================================================
extern "C" void kernel_launch(void* const* d_in, const int* in_sizes, int n_in,
                              void* d_out, int out_size) {
    const float* x          = (const float*)d_in[0];
    const int*   edge_index = (const int*)d_in[1];   // int64 in JAX -> int32 in harness
    const float* lin0_w     = (const float*)d_in[2];
    const float* lin0_b     = (const float*)d_in[3];
    const float* nn_w1      = (const float*)d_in[4];
    const float* nn_b1      = (const float*)d_in[5];
    const float* nn_w2      = (const float*)d_in[6];
    const float* nn_b2      = (const float*)d_in[7];
    const float* conv_root  = (const float*)d_in[8];
    const float* conv_bias  = (const float*)d_in[9];
    const float* lin1_w     = (const float*)d_in[10];
    const float* lin1_b     = (const float*)d_in[11];
    const float* lin2_w     = (const float*)d_in[12];
    const float* lin2_b     = (const float*)d_in[13];
    float* out_score = (float*)d_out;

    int n_nodes = in_sizes[0] / IN_FEAT;
    int n_edges = in_sizes[1] / 2;

    // K0: shared edge weight matrix (tiny)
    k0_edge_weight<<<1, 256>>>(nn_w1, nn_b1, nn_w2, nn_b2);

    // K1: 128-row tiles, 256 threads, 4x4 register tiling
    {
        int blocks = (n_nodes + TILE_R - 1) / TILE_R;
        k1_lin0<<<blocks, 256>>>(x, lin0_w, lin0_b, n_nodes);
    }

    // K2: 8 threads per edge, float4 reductions
    {
        long long total = (long long)n_edges * 8;
        int blocks = (int)((total + 255) / 256);
        k2_scatter<<<blocks, 256>>>(edge_index, n_edges, n_nodes);
    }

    // K3: 128-row tiles, 256 threads, 4x4 register tiling
    {
        int blocks = (n_nodes + TILE_R - 1) / TILE_R;
        k3_combine<<<blocks, 256>>>(conv_root, conv_bias, n_nodes);
    }

    // K4: 256-edge tiles, 256 threads
    {
        int blocks = (n_edges + TILE_E - 1) / TILE_E;
        k4_score<<<blocks, 256>>>(edge_index, lin1_w, lin1_b, lin2_w, lin2_b,
                                  out_score, n_edges, n_nodes);
    }
}

// round 9
// speedup vs baseline: 1.6733x; 1.0188x over previous
#include <cuda_runtime.h>
#include <stdint.h>

#define N_NODES 50000
#define N_EDGES 400000
#define IN_FEAT 64
#define H_DIM 32
#define TILE_R 128
#define TILE_E 256

// ---- device scratch (no runtime allocation allowed) ----
__device__ float g_hWe[N_NODES * H_DIM];   // (relu(x@W0+b0)) @ W_edge
__device__ float g_out[N_NODES * H_DIM];   // h@Wr + bias, then += scatter(hWe)
__device__ float g_We[H_DIM * H_DIM];      // shared per-edge weight matrix

__device__ __forceinline__ void red_add_v4(float* addr, float4 v) {
    asm volatile("red.global.v4.f32.add [%0], {%1, %2, %3, %4};"
                 :: "l"(addr), "f"(v.x), "f"(v.y), "f"(v.z), "f"(v.w)
                 : "memory");
}
__device__ __forceinline__ float relu(float v) { return v > 0.f ? v : 0.f; }

// XOR swizzle for transposed smem tiles: keeps float4 alignment (low 2 bits
// of row index untouched) while spreading banks across k.
__device__ __forceinline__ int swz(int k, int r) {
    return k * TILE_R + (r ^ (k & 28));
}

// ============================================================
// K0: W_edge = relu(nn_w1 + nn_b1) @ nn_w2 + nn_b2  (shared by all edges,
// since edge_attr == ones((E,1)))
// ============================================================
__global__ void k0_edge_weight(const float* __restrict__ nn_w1,
                               const float* __restrict__ nn_b1,
                               const float* __restrict__ nn_w2,
                               const float* __restrict__ nn_b2) {
    __shared__ float w1[H_DIM];
    int t = threadIdx.x;
    if (t < H_DIM) w1[t] = relu(nn_w1[t] + nn_b1[t]);
    __syncthreads();
    for (int i = t; i < H_DIM * H_DIM; i += blockDim.x) {
        float acc = nn_b2[i];
        #pragma unroll
        for (int k = 0; k < H_DIM; k++)
            acc += w1[k] * nn_w2[k * (H_DIM * H_DIM) + i];
        g_We[i] = acc;
    }
}

// ============================================================
// K1 (fused): h = relu(x@W0 + b0)  [smem only]
//             g_hWe = h @ W_edge
//             g_out = h @ conv_root + conv_bias   (scatter target init)
// Register-tiled 4x4 micro-tiles, 256 threads, 128-row tiles.
// Stage1: x (transposed smem) @ W0 -> h accs -> relu -> hT (reuse pool).
// Stage2: hT @ We and hT @ Wr simultaneously.
// ============================================================
__global__ void __launch_bounds__(256) k1_fused(
        const float* __restrict__ x,
        const float* __restrict__ lin0_w,
        const float* __restrict__ lin0_b,
        const float* __restrict__ conv_root,
        const float* __restrict__ conv_bias,
        int n_nodes) {
    __shared__ float pool[IN_FEAT * TILE_R];   // 32 KB: xT, then hT
    __shared__ float4 sw0[IN_FEAT * 8];        // 8 KB
    __shared__ float4 sWe[H_DIM * 8];          // 4 KB
    __shared__ float4 sWr[H_DIM * 8];          // 4 KB
    // total static smem = 49152 B exactly

    int tid  = threadIdx.x;
    int tx   = tid & 7;
    int ty   = tid >> 3;
    int row0 = blockIdx.x * TILE_R;
    int rb   = ty * 4;

    // weights to smem; biases to registers
    sw0[tid]       = ((const float4*)lin0_w)[tid];
    sw0[tid + 256] = ((const float4*)lin0_w)[tid + 256];
    sWe[tid]       = ((const float4*)g_We)[tid];
    sWr[tid]       = ((const float4*)conv_root)[tid];
    float4 b0 = __ldg((const float4*)lin0_b + tx);
    float4 bc = __ldg((const float4*)conv_bias + tx);

    // stage x tile transposed: 128 rows x 16 float4 = 2048 f4, 8 per thread
    #pragma unroll
    for (int it = 0; it < 8; it++) {
        int m = tid + 256 * it;
        int r = m >> 4, q = m & 15;
        float4 v = make_float4(0.f, 0.f, 0.f, 0.f);
        if (row0 + r < n_nodes)
            v = __ldg((const float4*)(x + (size_t)(row0 + r) * IN_FEAT) + q);
        pool[swz(4 * q + 0, r)] = v.x;
        pool[swz(4 * q + 1, r)] = v.y;
        pool[swz(4 * q + 2, r)] = v.z;
        pool[swz(4 * q + 3, r)] = v.w;
    }
    __syncthreads();

    // ---- stage 1: h micro-tile (4 rows x 4 cols) ----
    float4 a0 = b0, a1 = b0, a2 = b0, a3 = b0;
    #pragma unroll 8
    for (int k = 0; k < IN_FEAT; k++) {
        float4 xv = *(const float4*)&pool[swz(k, rb)];
        float4 wv = sw0[k * 8 + tx];
        a0.x = fmaf(xv.x, wv.x, a0.x); a0.y = fmaf(xv.x, wv.y, a0.y);
        a0.z = fmaf(xv.x, wv.z, a0.z); a0.w = fmaf(xv.x, wv.w, a0.w);
        a1.x = fmaf(xv.y, wv.x, a1.x); a1.y = fmaf(xv.y, wv.y, a1.y);
        a1.z = fmaf(xv.y, wv.z, a1.z); a1.w = fmaf(xv.y, wv.w, a1.w);
        a2.x = fmaf(xv.z, wv.x, a2.x); a2.y = fmaf(xv.z, wv.y, a2.y);
        a2.z = fmaf(xv.z, wv.z, a2.z); a2.w = fmaf(xv.z, wv.w, a2.w);
        a3.x = fmaf(xv.w, wv.x, a3.x); a3.y = fmaf(xv.w, wv.y, a3.y);
        a3.z = fmaf(xv.w, wv.z, a3.z); a3.w = fmaf(xv.w, wv.w, a3.w);
    }
    __syncthreads();  // all xT reads complete before pool is reused

    // write relu(h) transposed into pool: thread owns rows rb..rb+3,
    // cols 4tx..4tx+3
    {
        float4 rr[4] = {a0, a1, a2, a3};
        #pragma unroll
        for (int j = 0; j < 4; j++) {
            int r = rb + j;
            pool[swz(4 * tx + 0, r)] = relu(rr[j].x);
            pool[swz(4 * tx + 1, r)] = relu(rr[j].y);
            pool[swz(4 * tx + 2, r)] = relu(rr[j].z);
            pool[swz(4 * tx + 3, r)] = relu(rr[j].w);
        }
    }
    __syncthreads();

    // ---- stage 2: hWe = h@We (no bias), out = h@Wr + conv_bias ----
    float4 e0 = make_float4(0.f, 0.f, 0.f, 0.f), e1 = e0, e2 = e0, e3 = e0;
    float4 o0 = bc, o1 = bc, o2 = bc, o3 = bc;
    #pragma unroll 8
    for (int k = 0; k < H_DIM; k++) {
        float4 hv = *(const float4*)&pool[swz(k, rb)];
        float4 we = sWe[k * 8 + tx];
        float4 wr = sWr[k * 8 + tx];
        e0.x = fmaf(hv.x, we.x, e0.x); e0.y = fmaf(hv.x, we.y, e0.y);
        e0.z = fmaf(hv.x, we.z, e0.z); e0.w = fmaf(hv.x, we.w, e0.w);
        e1.x = fmaf(hv.y, we.x, e1.x); e1.y = fmaf(hv.y, we.y, e1.y);
        e1.z = fmaf(hv.y, we.z, e1.z); e1.w = fmaf(hv.y, we.w, e1.w);
        e2.x = fmaf(hv.z, we.x, e2.x); e2.y = fmaf(hv.z, we.y, e2.y);
        e2.z = fmaf(hv.z, we.z, e2.z); e2.w = fmaf(hv.z, we.w, e2.w);
        e3.x = fmaf(hv.w, we.x, e3.x); e3.y = fmaf(hv.w, we.y, e3.y);
        e3.z = fmaf(hv.w, we.z, e3.z); e3.w = fmaf(hv.w, we.w, e3.w);
        o0.x = fmaf(hv.x, wr.x, o0.x); o0.y = fmaf(hv.x, wr.y, o0.y);
        o0.z = fmaf(hv.x, wr.z, o0.z); o0.w = fmaf(hv.x, wr.w, o0.w);
        o1.x = fmaf(hv.y, wr.x, o1.x); o1.y = fmaf(hv.y, wr.y, o1.y);
        o1.z = fmaf(hv.y, wr.z, o1.z); o1.w = fmaf(hv.y, wr.w, o1.w);
        o2.x = fmaf(hv.z, wr.x, o2.x); o2.y = fmaf(hv.z, wr.y, o2.y);
        o2.z = fmaf(hv.z, wr.z, o2.z); o2.w = fmaf(hv.z, wr.w, o2.w);
        o3.x = fmaf(hv.w, wr.x, o3.x); o3.y = fmaf(hv.w, wr.y, o3.y);
        o3.z = fmaf(hv.w, wr.z, o3.z); o3.w = fmaf(hv.w, wr.w, o3.w);
    }

    float4 eres[4] = {e0, e1, e2, e3};
    float4 ores[4] = {o0, o1, o2, o3};
    #pragma unroll
    for (int i = 0; i < 4; i++) {
        int gr = row0 + rb + i;
        if (gr < n_nodes) {
            *(float4*)(g_hWe + (size_t)gr * H_DIM + tx * 4) = eres[i];
            *(float4*)(g_out + (size_t)gr * H_DIM + tx * 4) = ores[i];
        }
    }
}

// ============================================================
// K2: out[dst] += hWe[src]  — vector atomics. 8 threads per edge, each
// handles one float4 quarter via red.global.v4.f32.add.
// ============================================================
__global__ void k2_scatter(const int* __restrict__ edge_index,
                           int n_edges, int n_nodes) {
    long long tid = (long long)blockIdx.x * blockDim.x + threadIdx.x;
    int e = (int)(tid >> 3);
    if (e >= n_edges) return;
    int q = (int)(tid & 7);

    int src = __ldg(&edge_index[e]);            // edge_index[0][e]
    int dst = __ldg(&edge_index[n_edges + e]);  // edge_index[1][e]
    src = min(max(src, 0), n_nodes - 1);
    dst = min(max(dst, 0), n_nodes - 1);

    float4 v = __ldg((const float4*)(g_hWe + src * H_DIM) + q);
    red_add_v4(g_out + dst * H_DIM + q * 4, v);
}

// ============================================================
// K4: per-edge score, two-phase.
// Phase A: 8 lanes per edge gather out[src],out[dst] as whole coalesced
//          128B lines, form p = a*b, store to swizzled smem.
// Phase B: thread per edge: p@W1 (+bias, relu) then dot with W2.
// ============================================================
__global__ void __launch_bounds__(256) k4_score(
        const int* __restrict__ edge_index,
        const float* __restrict__ lin1_w,
        const float* __restrict__ lin1_b,
        const float* __restrict__ lin2_w,
        const float* __restrict__ lin2_b,
        float* __restrict__ out_score,
        int n_edges, int n_nodes) {
    __shared__ int   s_src[TILE_E];
    __shared__ int   s_dst[TILE_E];
    __shared__ float pT[TILE_E * H_DIM];      // 32 KB, swizzled
    __shared__ float sW1[H_DIM * 8];          // row-major [k][j]
    __shared__ float sB1[8], sW2[8];
    __shared__ float sB2;

    int tid = threadIdx.x;
    if (tid < H_DIM * 8) sW1[tid] = lin1_w[tid];
    if (tid < 8) { sB1[tid] = lin1_b[tid]; sW2[tid] = lin2_w[tid]; }
    if (tid == 0) sB2 = lin2_b[0];

    int e0 = blockIdx.x * TILE_E;
    {
        int e = e0 + tid;
        int s = 0, d = 0;
        if (e < n_edges) {
            s = min(max(__ldg(&edge_index[e]), 0), n_nodes - 1);
            d = min(max(__ldg(&edge_index[n_edges + e]), 0), n_nodes - 1);
        }
        s_src[tid] = s;
        s_dst[tid] = d;
    }
    __syncthreads();

    // Phase A: 2048 f4 (256 edges x 8 quarters), 8 per thread.
    #pragma unroll
    for (int it = 0; it < 8; it++) {
        int m = tid + 256 * it;
        int el = m >> 3, q = m & 7;
        int s = s_src[el], d = s_dst[el];
        float4 a = __ldg((const float4*)(g_out + (size_t)s * H_DIM) + q);
        float4 b = __ldg((const float4*)(g_out + (size_t)d * H_DIM) + q);
        float4 p = make_float4(a.x * b.x, a.y * b.y, a.z * b.z, a.w * b.w);
        *(float4*)&pT[el * H_DIM + 4 * (q ^ (el & 7))] = p;
    }
    __syncthreads();

    // Phase B: thread per edge
    float p[H_DIM];
    #pragma unroll
    for (int q = 0; q < 8; q++) {
        float4 v = *(const float4*)&pT[tid * H_DIM + 4 * (q ^ (tid & 7))];
        p[4 * q + 0] = v.x; p[4 * q + 1] = v.y;
        p[4 * q + 2] = v.z; p[4 * q + 3] = v.w;
    }

    float acc[8];
    #pragma unroll
    for (int j = 0; j < 8; j++) acc[j] = sB1[j];
    #pragma unroll
    for (int k = 0; k < H_DIM; k++) {
        float4 w0 = *(const float4*)&sW1[k * 8];      // broadcast LDS.128
        float4 w1 = *(const float4*)&sW1[k * 8 + 4];  // broadcast LDS.128
        float pk = p[k];
        acc[0] = fmaf(pk, w0.x, acc[0]); acc[1] = fmaf(pk, w0.y, acc[1]);
        acc[2] = fmaf(pk, w0.z, acc[2]); acc[3] = fmaf(pk, w0.w, acc[3]);
        acc[4] = fmaf(pk, w1.x, acc[4]); acc[5] = fmaf(pk, w1.y, acc[5]);
        acc[6] = fmaf(pk, w1.z, acc[6]); acc[7] = fmaf(pk, w1.w, acc[7]);
    }

    float score = sB2;
    #pragma unroll
    for (int j = 0; j < 8; j++) score = fmaf(relu(acc[j]), sW2[j], score);

    int e = e0 + tid;
    if (e < n_edges) out_score[e] = score;  // coalesced STG.32
}

// ============================================================
// launch
// ============================================================
extern "C" void kernel_launch(void* const* d_in, const int* in_sizes, int n_in,
                              void* d_out, int out_size) {
    const float* x          = (const float*)d_in[0];
    const int*   edge_index = (const int*)d_in[1];   // int64 in JAX -> int32 in harness
    const float* lin0_w     = (const float*)d_in[2];
    const float* lin0_b     = (const float*)d_in[3];
    const float* nn_w1      = (const float*)d_in[4];
    const float* nn_b1      = (const float*)d_in[5];
    const float* nn_w2      = (const float*)d_in[6];
    const float* nn_b2      = (const float*)d_in[7];
    const float* conv_root  = (const float*)d_in[8];
    const float* conv_bias  = (const float*)d_in[9];
    const float* lin1_w     = (const float*)d_in[10];
    const float* lin1_b     = (const float*)d_in[11];
    const float* lin2_w     = (const float*)d_in[12];
    const float* lin2_b     = (const float*)d_in[13];
    float* out_score = (float*)d_out;

    int n_nodes = in_sizes[0] / IN_FEAT;
    int n_edges = in_sizes[1] / 2;

    // K0: shared edge weight matrix (tiny)
    k0_edge_weight<<<1, 256>>>(nn_w1, nn_b1, nn_w2, nn_b2);

    // K1 fused: h (smem-only) -> g_hWe and g_out init
    {
        int blocks = (n_nodes + TILE_R - 1) / TILE_R;
        k1_fused<<<blocks, 256>>>(x, lin0_w, lin0_b, conv_root, conv_bias,
                                  n_nodes);
    }

    // K2: 8 threads per edge, float4 reductions into g_out
    {
        long long total = (long long)n_edges * 8;
        int blocks = (int)((total + 255) / 256);
        k2_scatter<<<blocks, 256>>>(edge_index, n_edges, n_nodes);
    }

    // K4: 256-edge tiles, 256 threads
    {
        int blocks = (n_edges + TILE_E - 1) / TILE_E;
        k4_score<<<blocks, 256>>>(edge_index, lin1_w, lin1_b, lin2_w, lin2_b,
                                  out_score, n_edges, n_nodes);
    }
}